// round 2
// baseline (speedup 1.0000x reference)
#include <cuda_runtime.h>

// Problem constants
#define BB      2
#define SS      2048
#define DIMM    1024
#define NHEADS  16
#define HDIM    64
#define WIN     256
#define NTOK    (BB*SS)          // 4096

// Scratch for Q/K/V projections (device globals: allocation-free)
__device__ float g_q[NTOK * DIMM];
__device__ float g_k[NTOK * DIMM];
__device__ float g_v[NTOK * DIMM];

// ---------------- packed f32x2 helpers (Blackwell FFMA2 path) ----------------
typedef unsigned long long u64;

__device__ __forceinline__ u64 pack2(float lo, float hi) {
    u64 r; asm("mov.b64 %0, {%1, %2};" : "=l"(r) : "f"(lo), "f"(hi)); return r;
}
__device__ __forceinline__ float2 unpack2(u64 v) {
    float2 r; asm("mov.b64 {%0, %1}, %2;" : "=f"(r.x), "=f"(r.y) : "l"(v)); return r;
}
__device__ __forceinline__ u64 fma2(u64 a, u64 b, u64 c) {
    u64 d; asm("fma.rn.f32x2 %0, %1, %2, %3;" : "=l"(d) : "l"(a), "l"(b), "l"(c)); return d;
}
__device__ __forceinline__ u64 mul2(u64 a, u64 b) {
    u64 d; asm("mul.rn.f32x2 %0, %1, %2;" : "=l"(d) : "l"(a), "l"(b)); return d;
}
__device__ __forceinline__ u64 add2(u64 a, u64 b) {
    u64 d; asm("add.rn.f32x2 %0, %1, %2;" : "=l"(d) : "l"(a), "l"(b)); return d;
}
__device__ __forceinline__ float ex2_approx(float x) {
    float r; asm("ex2.approx.f32 %0, %1;" : "=f"(r) : "f"(x)); return r;
}

union F4U { float4 f; u64 u[2]; };

// ---------------- Kernel 1: fused QKV projection GEMM ----------------
// C[n,o] = sum_k X[n,k] * W[o,k] + bias[o]    (NT gemm, both K-contiguous)
// 128x128 block tile, BK=16, 256 threads, 8x8 per thread via f32x2.
// Global loads for slab k+1 are issued before the barrier of slab k (reg prefetch).
#define BM  128
#define BN  128
#define BKK 16

__global__ void __launch_bounds__(256, 2) qkv_gemm(
    const float* __restrict__ X,
    const float* __restrict__ Wq, const float* __restrict__ bq,
    const float* __restrict__ Wk, const float* __restrict__ bk,
    const float* __restrict__ Wv, const float* __restrict__ bv)
{
    const float* W; const float* bias; float* C;
    if (blockIdx.z == 0)      { W = Wq; bias = bq; C = g_q; }
    else if (blockIdx.z == 1) { W = Wk; bias = bk; C = g_k; }
    else                      { W = Wv; bias = bv; C = g_v; }

    __shared__ float As[BKK][BM];   // transposed: As[k][row]
    __shared__ float Bs[BKK][BN];   // transposed: Bs[k][col]

    const int row0 = blockIdx.y * BM;
    const int col0 = blockIdx.x * BN;
    const int tid  = threadIdx.x;
    const int tx   = tid & 15;      // 16 columns of threads
    const int ty   = tid >> 4;      // 16 rows of threads
    const int lr   = tid >> 2;      // load row (0..63)
    const int lc   = tid & 3;       // load float4 col (0..3)

    u64 acc[8][4];
    #pragma unroll
    for (int m = 0; m < 8; m++)
        #pragma unroll
        for (int n = 0; n < 4; n++) acc[m][n] = 0ull;

    const float* Xp = X + (row0 + lr) * DIMM + lc * 4;
    const float* Wp = W + (col0 + lr) * DIMM + lc * 4;

    // register prefetch of the first slab
    float4 pa[2], pb[2];
    #pragma unroll
    for (int hh = 0; hh < 2; hh++) {
        pa[hh] = *(const float4*)(Xp + hh * 64 * DIMM);
        pb[hh] = *(const float4*)(Wp + hh * 64 * DIMM);
    }

    for (int k0 = 0; k0 < DIMM; k0 += BKK) {
        // commit prefetched slab to smem
        #pragma unroll
        for (int hh = 0; hh < 2; hh++) {
            const int r = lr + hh * 64;
            As[lc*4+0][r] = pa[hh].x; As[lc*4+1][r] = pa[hh].y;
            As[lc*4+2][r] = pa[hh].z; As[lc*4+3][r] = pa[hh].w;
            Bs[lc*4+0][r] = pb[hh].x; Bs[lc*4+1][r] = pb[hh].y;
            Bs[lc*4+2][r] = pb[hh].z; Bs[lc*4+3][r] = pb[hh].w;
        }
        __syncthreads();

        // issue next slab's global loads early (latency overlap with math)
        if (k0 + BKK < DIMM) {
            #pragma unroll
            for (int hh = 0; hh < 2; hh++) {
                pa[hh] = *(const float4*)(Xp + hh * 64 * DIMM + k0 + BKK);
                pb[hh] = *(const float4*)(Wp + hh * 64 * DIMM + k0 + BKK);
            }
        }

        #pragma unroll
        for (int kk = 0; kk < BKK; kk++) {
            float4 a0 = *(const float4*)&As[kk][ty * 8];
            float4 a1 = *(const float4*)&As[kk][ty * 8 + 4];
            F4U b0; b0.f = *(const float4*)&Bs[kk][tx * 8];
            F4U b1; b1.f = *(const float4*)&Bs[kk][tx * 8 + 4];
            u64 a2[8];
            a2[0] = pack2(a0.x, a0.x); a2[1] = pack2(a0.y, a0.y);
            a2[2] = pack2(a0.z, a0.z); a2[3] = pack2(a0.w, a0.w);
            a2[4] = pack2(a1.x, a1.x); a2[5] = pack2(a1.y, a1.y);
            a2[6] = pack2(a1.z, a1.z); a2[7] = pack2(a1.w, a1.w);
            u64 bb[4] = { b0.u[0], b0.u[1], b1.u[0], b1.u[1] };
            #pragma unroll
            for (int m = 0; m < 8; m++)
                #pragma unroll
                for (int n = 0; n < 4; n++)
                    acc[m][n] = fma2(a2[m], bb[n], acc[m][n]);
        }
        __syncthreads();
    }

    // epilogue: bias + store (bias is zeros in this problem but add anyway)
    float bias8[8];
    #pragma unroll
    for (int n = 0; n < 8; n++) bias8[n] = bias[col0 + tx * 8 + n];

    #pragma unroll
    for (int m = 0; m < 8; m++) {
        float o[8];
        #pragma unroll
        for (int n = 0; n < 4; n++) {
            float2 v = unpack2(acc[m][n]);
            o[2*n]   = v.x + bias8[2*n];
            o[2*n+1] = v.y + bias8[2*n+1];
        }
        float* cp = C + (row0 + ty * 8 + m) * DIMM + col0 + tx * 8;
        *(float4*)(cp)     = make_float4(o[0], o[1], o[2], o[3]);
        *(float4*)(cp + 4) = make_float4(o[4], o[5], o[6], o[7]);
    }
}

// ---------------- Kernel 2: windowed flash attention ----------------
// Mask: key j visible to query i iff j < i + WIN  (lookahead-causal, grows with i).
// One query per thread, 128 queries per block, K/V tiles of 64 in smem.
// Scores are computed in log2 domain: q pre-scaled by log2(e)/sqrt(D), softmax
// uses ex2.approx — same MUFU count as __expf but no extra multiply per key.
#define KT 64

__global__ void __launch_bounds__(128) attn_kernel(float* __restrict__ out)
{
    __shared__ float Ks[KT][HDIM];
    __shared__ float Vs[KT][HDIM];

    const int b = blockIdx.z;
    const int h = blockIdx.y;
    // launch heavy (late) query tiles first to reduce tail imbalance
    const int qt    = (int)gridDim.x - 1 - (int)blockIdx.x;
    const int qbase = qt * 128;
    const int t     = threadIdx.x;
    const int i     = qbase + t;

    // load q row, pre-scaled by log2(e)/sqrt(D)
    u64 q2[32];
    {
        const float4* qp = (const float4*)(g_q + (b * SS + i) * DIMM + h * HDIM);
        const float scale = 0.125f * 1.4426950408889634f;  // log2(e)/sqrt(64)
        #pragma unroll
        for (int d4 = 0; d4 < 16; d4++) {
            float4 v = qp[d4];
            q2[2*d4]   = pack2(v.x * scale, v.y * scale);
            q2[2*d4+1] = pack2(v.z * scale, v.w * scale);
        }
    }

    u64 acc[32];
    #pragma unroll
    for (int d = 0; d < 32; d++) acc[d] = 0ull;
    float mrow = -3.0e38f, lrow = 0.0f;   // mrow/lrow live in log2 domain

    const int jend = min(SS, qbase + 127 + WIN);  // exclusive upper key bound for this block
    const float* Kbase = g_k + (b * SS) * DIMM + h * HDIM;
    const float* Vbase = g_v + (b * SS) * DIMM + h * HDIM;

    for (int j0 = 0; j0 < jend; j0 += KT) {
        const int nvalid = min(KT, jend - j0);
        __syncthreads();
        #pragma unroll
        for (int u = 0; u < 8; u++) {
            int idx = t + u * 128;           // 0..1023 float4 slots
            int row = idx >> 4;
            int c4  = idx & 15;
            if (row < nvalid) {
                ((float4*)Ks[row])[c4] = ((const float4*)(Kbase + (j0 + row) * DIMM))[c4];
                ((float4*)Vs[row])[c4] = ((const float4*)(Vbase + (j0 + row) * DIMM))[c4];
            }
        }
        __syncthreads();

        const int jlim = min(nvalid, i + WIN - j0);   // per-thread window mask
        for (int jj = 0; jj < jlim; jj++) {
            // ---- score = (q*log2e/8) . k  (two independent f32x2 chains) ----
            const float4* kr = (const float4*)Ks[jj];
            u64 sa = 0ull, sb = 0ull;
            #pragma unroll
            for (int d4 = 0; d4 < 16; d4 += 2) {
                F4U k0u; k0u.f = kr[d4];
                F4U k1u; k1u.f = kr[d4 + 1];
                sa = fma2(q2[2*d4],     k0u.u[0], sa);
                sb = fma2(q2[2*d4+1],   k0u.u[1], sb);
                sa = fma2(q2[2*d4+2],   k1u.u[0], sa);
                sb = fma2(q2[2*d4+3],   k1u.u[1], sb);
            }
            float2 sv = unpack2(add2(sa, sb));
            float s = sv.x + sv.y;   // log2-domain score

            // ---- online softmax, lazy rescale (base-2) ----
            if (s > mrow) {
                float corr = ex2_approx(mrow - s);
                mrow = s;
                lrow *= corr;
                u64 c2 = pack2(corr, corr);
                #pragma unroll
                for (int d = 0; d < 32; d++) acc[d] = mul2(acc[d], c2);
            }
            float p = ex2_approx(s - mrow);
            lrow += p;
            u64 p2 = pack2(p, p);

            // ---- acc += p * v ----
            const float4* vr = (const float4*)Vs[jj];
            #pragma unroll
            for (int d4 = 0; d4 < 16; d4++) {
                F4U vu; vu.f = vr[d4];
                acc[2*d4]   = fma2(p2, vu.u[0], acc[2*d4]);
                acc[2*d4+1] = fma2(p2, vu.u[1], acc[2*d4+1]);
            }
        }
    }

    // output layout [B,S,H,D] == row (b*S+i)*DIM + h*64 + d
    const float inv = 1.0f / lrow;
    float* op = out + (b * SS + i) * DIMM + h * HDIM;
    #pragma unroll
    for (int d4 = 0; d4 < 16; d4++) {
        float2 v0 = unpack2(acc[2*d4]);
        float2 v1 = unpack2(acc[2*d4+1]);
        ((float4*)op)[d4] = make_float4(v0.x * inv, v0.y * inv, v1.x * inv, v1.y * inv);
    }
}

// ---------------- launch ----------------
extern "C" void kernel_launch(void* const* d_in, const int* in_sizes, int n_in,
                              void* d_out, int out_size)
{
    const float* x  = (const float*)d_in[0];
    const float* Wq = (const float*)d_in[1];
    const float* bq = (const float*)d_in[2];
    const float* Wk = (const float*)d_in[3];
    const float* bk = (const float*)d_in[4];
    const float* Wv = (const float*)d_in[5];
    const float* bv = (const float*)d_in[6];
    float* out = (float*)d_out;

    dim3 ggrid(DIMM / BN, NTOK / BM, 3);   // 8 x 32 x 3 = 768 blocks
    qkv_gemm<<<ggrid, 256>>>(x, Wq, bq, Wk, bk, Wv, bv);

    dim3 agrid(SS / 128, NHEADS, BB);      // 16 x 16 x 2 = 512 blocks
    attn_kernel<<<agrid, 128>>>(out);
}